// round 8
// baseline (speedup 1.0000x reference)
#include <cuda_runtime.h>
#include <cstdint>
#include <cstddef>

// Problem constants
#define BB 16
#define CC 256
#define HH 64
#define WW 64
#define HW (HH*WW)
#define DD 4          // max displacement
#define PP 9          // patch = 2d+1

// Tiling
#define TI 4          // rows per block tile
#define KC 8          // channels per staged chunk
#define NCHUNK (CC/KC)
#define XS 72         // x smem row stride (floats); LDS.128 phase residues conflict-free
#define YR (TI + 2*DD)   // 12 y rows per tile
#define YS 72         // y smem row stride (floats); same conflict-free property

#define NTH 576       // 18 warps; warp w: di = w>>1, sub = w&1 (column half)
#define NBUF 3        // triple buffer -> single barrier per chunk

#define XSZ (KC*TI*XS)     // 2304 floats
#define YSZ (KC*YR*YS)     // 6912 floats
#define BUFSZ (XSZ+YSZ)    // 9216 floats
#define SMEM_BYTES (NBUF*BUFSZ*4)   // 110592 B; x2 blocks = 216 KB/SM

__device__ __forceinline__ uint32_t s2u(const void* p) {
    return (uint32_t)__cvta_generic_to_shared(p);
}
__device__ __forceinline__ void cpa8(uint32_t s, const float* g) {
    asm volatile("cp.async.ca.shared.global [%0], [%1], 8;\n" :: "r"(s), "l"(g));
}
__device__ __forceinline__ void cp_commit() {
    asm volatile("cp.async.commit_group;\n");
}

// Stage one 8-channel chunk into buffer sb. Shift/mask index math only.
__device__ __forceinline__ void stage_chunk(float* sb,
                                            const float* __restrict__ xb,
                                            const float* __restrict__ yb,
                                            int c0, int i0, int tid, int vmask)
{
    // x: KC*TI*32 = 1024 float2 jobs, thread-strided (<=2 per thread)
    for (int idx = tid; idx < KC * TI * 32; idx += NTH) {
        int c    = idx >> 7;
        int rr   = (idx >> 5) & 3;
        int col2 = idx & 31;
        uint32_t s = s2u(sb + c * (TI * XS) + rr * XS + col2 * 2);
        cpa8(s, xb + (size_t)(c0 + c) * HW + (i0 + rr) * WW + col2 * 2);
    }
    // y: 96 row-jobs, one warp per job (18 warps), 32 f2 per row
    int w = tid >> 5, lane = tid & 31;
    for (int job = w; job < KC * YR; job += 18) {
        int q = job >> 3;
        int c = job & 7;
        if ((vmask >> q) & 1) {
            int gi = i0 + q - DD;
            uint32_t s = s2u(sb + XSZ + c * (YR * YS) + q * YS + DD + lane * 2);
            cpa8(s, yb + (size_t)(c0 + c) * HW + gi * WW + lane * 2);
        }
    }
}

// Compute: 4 columns x 9 dj per thread, 36 FFMA per channel.
__device__ __forceinline__ void compute_chunk(const float* sb, float acc[4][PP],
                                              int r, int di, int jseg)
{
    #pragma unroll
    for (int c = 0; c < KC; ++c) {
        const float4* xr4 = reinterpret_cast<const float4*>(
            sb + c * (TI * XS) + r * XS + jseg);
        const float4* yr4 = reinterpret_cast<const float4*>(
            sb + XSZ + c * (YR * YS) + (r + di) * YS + jseg);

        float4 xv = xr4[0];
        float xk[4] = {xv.x, xv.y, xv.z, xv.w};

        // group A: dj 0..3 needs y[jseg .. jseg+6]  -> f4[0], f4[1]
        {
            float4 a = yr4[0], b = yr4[1];
            float yv[8] = {a.x, a.y, a.z, a.w, b.x, b.y, b.z, b.w};
            #pragma unroll
            for (int k = 0; k < 4; ++k)
                #pragma unroll
                for (int d = 0; d < 4; ++d)
                    acc[k][d] += xk[k] * yv[k + d];
        }
        // group B: dj 4..8 needs y[jseg+4 .. jseg+11] -> f4[1], f4[2]
        {
            float4 a = yr4[1], b = yr4[2];
            float yv[8] = {a.x, a.y, a.z, a.w, b.x, b.y, b.z, b.w};
            #pragma unroll
            for (int k = 0; k < 4; ++k)
                #pragma unroll
                for (int d = 4; d < PP; ++d)
                    acc[k][d] += xk[k] * yv[k + d - 4];
        }
    }
}

__global__ __launch_bounds__(NTH, 2)
void corr_kernel(const float* __restrict__ x,
                 const float* __restrict__ y,
                 float* __restrict__ out)
{
    extern __shared__ float smem[];   // [NBUF][BUFSZ]

    const int bx   = blockIdx.x;
    const int b    = bx >> 4;
    const int i0   = (bx & 15) * TI;
    const int tid  = threadIdx.x;
    const int w    = tid >> 5;
    const int di   = w >> 1;          // 0..8
    const int sub  = w & 1;           // column half
    const int lane = tid & 31;
    const int r    = lane & 3;        // local row 0..3
    const int jq   = lane >> 2;       // 0..7
    const int jseg = (sub * 8 + jq) * 4;   // column start, multiple of 4

    const float* xb = x + (size_t)b * CC * HW;
    const float* yb = y + (size_t)b * CC * HW;

    // Valid-row mask for the y tile (rows i0-4 .. i0+7)
    int vmask = 0;
    #pragma unroll
    for (int q = 0; q < YR; ++q) {
        int gi = i0 + q - DD;
        if (gi >= 0 && gi < HH) vmask |= (1 << q);
    }

    // Zero the y regions of all buffers once; halo slots never rewritten.
    {
        const float4 z = make_float4(0.f, 0.f, 0.f, 0.f);
        #pragma unroll
        for (int nb = 0; nb < NBUF; ++nb) {
            float4* yz = reinterpret_cast<float4*>(smem + nb * BUFSZ + XSZ);
            for (int idx = tid; idx < YSZ / 4; idx += NTH) yz[idx] = z;
        }
    }
    __syncthreads();

    float acc[4][PP];
    #pragma unroll
    for (int k = 0; k < 4; ++k)
        #pragma unroll
        for (int d = 0; d < PP; ++d)
            acc[k][d] = 0.0f;

    // Prime two chunks
    stage_chunk(smem + 0 * BUFSZ, xb, yb, 0, i0, tid, vmask);
    cp_commit();
    stage_chunk(smem + 1 * BUFSZ, xb, yb, KC, i0, tid, vmask);
    cp_commit();

    // wait(k) -> sync -> compute(k) -> stage(k+2): stage writes buf (k-1)%3,
    // every thread is past sync(k) which follows its compute(k-1) reads.
    int cur = 0, nxt = 2;
    for (int k = 0; k < NCHUNK; ++k) {
        if (k + 1 < NCHUNK) {
            asm volatile("cp.async.wait_group 1;\n");
        } else {
            asm volatile("cp.async.wait_group 0;\n");
        }
        __syncthreads();
        compute_chunk(smem + cur * BUFSZ, acc, r, di, jseg);
        if (k + 2 < NCHUNK) {
            stage_chunk(smem + nxt * BUFSZ, xb, yb, (k + 2) * KC, i0, tid, vmask);
            cp_commit();
        }
        cur = (cur + 1 == NBUF) ? 0 : cur + 1;
        nxt = (nxt + 1 == NBUF) ? 0 : nxt + 1;
    }

    // Write out: out[b, di*9+d, i0+r, jseg..jseg+3]
    const float scale = 1.0f / (float)CC;
    #pragma unroll
    for (int d = 0; d < PP; ++d) {
        int ch = di * PP + d;
        float* o = out + (((size_t)b * (PP * PP) + ch) * HH + (i0 + r)) * WW + jseg;
        float4 v;
        v.x = acc[0][d] * scale;
        v.y = acc[1][d] * scale;
        v.z = acc[2][d] * scale;
        v.w = acc[3][d] * scale;
        reinterpret_cast<float4*>(o)[0] = v;
    }
}

extern "C" void kernel_launch(void* const* d_in, const int* in_sizes, int n_in,
                              void* d_out, int out_size)
{
    const float* x = (const float*)d_in[0];
    const float* y = (const float*)d_in[1];
    float* out = (float*)d_out;
    (void)in_sizes; (void)n_in; (void)out_size;

    cudaFuncSetAttribute(corr_kernel,
                         cudaFuncAttributeMaxDynamicSharedMemorySize, SMEM_BYTES);

    dim3 grid(BB * (HH / TI));   // 256 blocks
    dim3 block(NTH);             // 18 warps
    corr_kernel<<<grid, block, SMEM_BYTES>>>(x, y, out);
}

// round 10
// speedup vs baseline: 1.1613x; 1.1613x over previous
#include <cuda_runtime.h>
#include <cstdint>
#include <cstddef>

// Problem constants
#define BB 16
#define CC 256
#define HH 64
#define WW 64
#define HW (HH*WW)
#define DD 4          // max displacement
#define PP 9          // patch = 2d+1

// Tiling
#define TI 4          // rows per block tile
#define KC 8          // channels per staged chunk
#define NCHUNK (CC/KC)
#define XS 66         // x smem row stride (floats); LDS.64 phase residues conflict-free
#define YR (TI + 2*DD)   // 12 y rows per tile
#define YS 74         // y smem row stride (floats); LDS.64 phase residues conflict-free

#define NTH 288       // 9 warps; warp w == displacement row di
#define NBUF 3        // triple buffer -> single barrier per chunk

#define XSZ (KC*TI*XS)     // 2112 floats
#define YSZ (KC*YR*YS)     // 7104 floats
#define BUFSZ (XSZ+YSZ)    // 9216 floats
#define SMEM_BYTES (NBUF*BUFSZ*4)   // 110592 B; x2 blocks/SM = 221 KB

__device__ __forceinline__ uint32_t s2u(const void* p) {
    return (uint32_t)__cvta_generic_to_shared(p);
}
__device__ __forceinline__ void cpa8(uint32_t s, const float* g) {
    asm volatile("cp.async.ca.shared.global [%0], [%1], 8;\n" :: "r"(s), "l"(g));
}
__device__ __forceinline__ void cp_commit() {
    asm volatile("cp.async.commit_group;\n");
}

// Stage one 8-channel chunk into buffer sb. Shift/mask index math only.
__device__ __forceinline__ void stage_chunk(float* sb,
                                            const float* __restrict__ xb,
                                            const float* __restrict__ yb,
                                            int c0, int i0, int tid, int vmask)
{
    // x: KC*TI*32 = 1024 float2 jobs, thread-strided
    for (int idx = tid; idx < KC * TI * 32; idx += NTH) {
        int c    = idx >> 7;
        int rr   = (idx >> 5) & 3;
        int col2 = idx & 31;
        uint32_t s = s2u(sb + c * (TI * XS) + rr * XS + col2 * 2);
        cpa8(s, xb + (size_t)(c0 + c) * HW + (i0 + rr) * WW + col2 * 2);
    }
    // y: 96 row-jobs, one warp per job, 32 f2 per row
    int w = tid >> 5, lane = tid & 31;
    for (int job = w; job < KC * YR; job += 9) {
        int q = job >> 3;
        int c = job & 7;
        if ((vmask >> q) & 1) {
            int gi = i0 + q - DD;
            uint32_t s = s2u(sb + XSZ + c * (YR * YS) + q * YS + DD + lane * 2);
            cpa8(s, yb + (size_t)(c0 + c) * HW + gi * WW + lane * 2);
        }
    }
}

// Compute: 8 columns x 9 dj per thread, 72 scalar FFMA per channel.
__device__ __forceinline__ void compute_chunk(const float* sb, float acc[8][PP],
                                              int r, int di, int jseg)
{
    #pragma unroll
    for (int c = 0; c < KC; ++c) {
        const float2* xr2 = reinterpret_cast<const float2*>(
            sb + c * (TI * XS) + r * XS + jseg);
        const float2* yr2 = reinterpret_cast<const float2*>(
            sb + XSZ + c * (YR * YS) + (r + di) * YS + jseg);

        float xv[8], yv[16];
        #pragma unroll
        for (int m = 0; m < 4; ++m) {
            float2 v = xr2[m];
            xv[2 * m] = v.x; xv[2 * m + 1] = v.y;
        }
        #pragma unroll
        for (int m = 0; m < 8; ++m) {
            float2 v = yr2[m];
            yv[2 * m] = v.x; yv[2 * m + 1] = v.y;
        }
        #pragma unroll
        for (int k = 0; k < 8; ++k)
            #pragma unroll
            for (int d = 0; d < PP; ++d)
                acc[k][d] += xv[k] * yv[k + d];
    }
}

__global__ __launch_bounds__(NTH, 2)
void corr_kernel(const float* __restrict__ x,
                 const float* __restrict__ y,
                 float* __restrict__ out)
{
    extern __shared__ float smem[];   // [NBUF][BUFSZ]

    const int bx   = blockIdx.x;
    const int b    = bx >> 4;
    const int i0   = (bx & 15) * TI;
    const int tid  = threadIdx.x;
    const int di   = tid >> 5;
    const int lane = tid & 31;
    const int r    = lane & 3;
    const int jseg = (lane >> 2) * 8;

    const float* xb = x + (size_t)b * CC * HW;
    const float* yb = y + (size_t)b * CC * HW;

    // Valid-row mask for the y tile (rows i0-4 .. i0+7)
    int vmask = 0;
    #pragma unroll
    for (int q = 0; q < YR; ++q) {
        int gi = i0 + q - DD;
        if (gi >= 0 && gi < HH) vmask |= (1 << q);
    }

    // Zero the y regions of all buffers once; halo slots never rewritten.
    {
        const float2 z = make_float2(0.f, 0.f);
        #pragma unroll
        for (int nb = 0; nb < NBUF; ++nb) {
            float2* yz = reinterpret_cast<float2*>(smem + nb * BUFSZ + XSZ);
            for (int idx = tid; idx < YSZ / 2; idx += NTH) yz[idx] = z;
        }
    }
    __syncthreads();

    float acc[8][PP];
    #pragma unroll
    for (int k = 0; k < 8; ++k)
        #pragma unroll
        for (int d = 0; d < PP; ++d)
            acc[k][d] = 0.0f;

    // Prime two chunks
    stage_chunk(smem + 0 * BUFSZ, xb, yb, 0, i0, tid, vmask);
    cp_commit();
    stage_chunk(smem + 1 * BUFSZ, xb, yb, KC, i0, tid, vmask);
    cp_commit();

    // wait(k) -> sync -> compute(k) -> stage(k+2): stage writes buf (k-1)%3;
    // every thread is past sync(k), which follows its compute(k-1) reads of
    // that buffer. One barrier per chunk.
    int cur = 0, nxt = 2;
    for (int k = 0; k < NCHUNK; ++k) {
        if (k + 1 < NCHUNK) {
            asm volatile("cp.async.wait_group 1;\n");   // chunk k's group done
        } else {
            asm volatile("cp.async.wait_group 0;\n");
        }
        __syncthreads();
        compute_chunk(smem + cur * BUFSZ, acc, r, di, jseg);
        if (k + 2 < NCHUNK) {
            stage_chunk(smem + nxt * BUFSZ, xb, yb, (k + 2) * KC, i0, tid, vmask);
            cp_commit();
        }
        cur = (cur + 1 == NBUF) ? 0 : cur + 1;
        nxt = (nxt + 1 == NBUF) ? 0 : nxt + 1;
    }

    // Write out: out[b, di*9+d, i0+r, jseg..jseg+7]
    const float scale = 1.0f / (float)CC;
    #pragma unroll
    for (int d = 0; d < PP; ++d) {
        int ch = di * PP + d;
        float* o = out + (((size_t)b * (PP * PP) + ch) * HH + (i0 + r)) * WW + jseg;
        float4 v0, v1;
        v0.x = acc[0][d] * scale; v0.y = acc[1][d] * scale;
        v0.z = acc[2][d] * scale; v0.w = acc[3][d] * scale;
        v1.x = acc[4][d] * scale; v1.y = acc[5][d] * scale;
        v1.z = acc[6][d] * scale; v1.w = acc[7][d] * scale;
        reinterpret_cast<float4*>(o)[0] = v0;
        reinterpret_cast<float4*>(o)[1] = v1;
    }
}

extern "C" void kernel_launch(void* const* d_in, const int* in_sizes, int n_in,
                              void* d_out, int out_size)
{
    const float* x = (const float*)d_in[0];
    const float* y = (const float*)d_in[1];
    float* out = (float*)d_out;
    (void)in_sizes; (void)n_in; (void)out_size;

    cudaFuncSetAttribute(corr_kernel,
                         cudaFuncAttributeMaxDynamicSharedMemorySize, SMEM_BYTES);

    dim3 grid(BB * (HH / TI));   // 256 blocks
    dim3 block(NTH);             // 9 warps
    corr_kernel<<<grid, block, SMEM_BYTES>>>(x, y, out);
}